// round 1
// baseline (speedup 1.0000x reference)
#include <cuda_runtime.h>
#include <cstdint>

// Problem constants
#define BB   2
#define SS   2048
#define TT   2048
#define CHN  1024
#define NH   16
#define HD   64
#define MM   (BB * SS)   // 4096 rows

// Scratch (device globals: allocation-free rule)
__device__ float g_Q[(size_t)MM * CHN];
__device__ float g_K[(size_t)MM * CHN];
__device__ float g_V[(size_t)MM * CHN];
__device__ float g_A[(size_t)MM * CHN];

// ---------------- helpers ----------------
__device__ __forceinline__ uint32_t f2tf(float x) {
    uint32_t u;
    asm("cvt.rna.tf32.f32 %0, %1;\n" : "=r"(u) : "f"(x));
    return u;
}
__device__ __forceinline__ float f2tf_f(float x) {
    return __uint_as_float(f2tf(x));
}
__device__ __forceinline__ uint32_t fu(float x) { return __float_as_uint(x); }

// D(16x8) += A(16x8, tf32, row) * B(8x8, tf32, col)
__device__ __forceinline__ void mma8(float c[4], const uint32_t a[4], const uint32_t b[2]) {
    asm volatile(
        "mma.sync.aligned.m16n8k8.row.col.f32.tf32.tf32.f32 "
        "{%0,%1,%2,%3}, {%4,%5,%6,%7}, {%8,%9}, {%0,%1,%2,%3};\n"
        : "+f"(c[0]), "+f"(c[1]), "+f"(c[2]), "+f"(c[3])
        : "r"(a[0]), "r"(a[1]), "r"(a[2]), "r"(a[3]), "r"(b[0]), "r"(b[1]));
}

// ---------------- GEMM: C[M=4096,N=1024] = X[M,1024] @ W[1024,1024] + bias ----------------
// Optional epilogue scale by maskScale[row*TT] (for output projection).
// BM=128, BN=128, BK=32, 256 threads (8 warps as 4m x 2n), warp tile 32x64.
__global__ void __launch_bounds__(256) gemm_bias_kernel(
    const float* __restrict__ X, const float* __restrict__ W,
    const float* __restrict__ bias, float* __restrict__ C,
    const float* __restrict__ maskScale)
{
    __shared__ float Xs[128 * 36];   // [row][k], stride 36 -> conflict-free frags
    __shared__ float Ws[32 * 132];   // [k][col], stride 132 -> conflict-free frags

    const int tid  = threadIdx.x;
    const int lane = tid & 31;
    const int warp = tid >> 5;
    const int g    = lane >> 2;
    const int tg   = lane & 3;
    const int wm   = warp >> 1;   // 0..3
    const int wn   = warp & 1;    // 0..1
    const int m0   = blockIdx.y * 128;
    const int n0   = blockIdx.x * 128;

    float c[2][8][4];
#pragma unroll
    for (int mt = 0; mt < 2; mt++)
#pragma unroll
        for (int nt = 0; nt < 8; nt++)
#pragma unroll
            for (int e = 0; e < 4; e++) c[mt][nt][e] = 0.f;

    for (int kt = 0; kt < 1024; kt += 32) {
        // Load X tile 128x32 and W tile 32x128 (convert to tf32 at store)
#pragma unroll
        for (int i = 0; i < 4; i++) {
            int idx = i * 256 + tid;
            // X: 128 rows x 8 float4
            {
                int r  = idx >> 3;
                int cc = (idx & 7) * 4;
                float4 v = *(const float4*)&X[(size_t)(m0 + r) * 1024 + kt + cc];
                Xs[r * 36 + cc + 0] = f2tf_f(v.x);
                Xs[r * 36 + cc + 1] = f2tf_f(v.y);
                Xs[r * 36 + cc + 2] = f2tf_f(v.z);
                Xs[r * 36 + cc + 3] = f2tf_f(v.w);
            }
            // W: 32 rows x 32 float4
            {
                int r  = idx >> 5;
                int cc = (idx & 31) * 4;
                float4 v = *(const float4*)&W[(size_t)(kt + r) * 1024 + n0 + cc];
                Ws[r * 132 + cc + 0] = f2tf_f(v.x);
                Ws[r * 132 + cc + 1] = f2tf_f(v.y);
                Ws[r * 132 + cc + 2] = f2tf_f(v.z);
                Ws[r * 132 + cc + 3] = f2tf_f(v.w);
            }
        }
        __syncthreads();

#pragma unroll
        for (int ks = 0; ks < 32; ks += 8) {
            uint32_t a[2][4];
#pragma unroll
            for (int mt = 0; mt < 2; mt++) {
                int r = wm * 32 + mt * 16;
                a[mt][0] = fu(Xs[(r + g) * 36 + ks + tg]);
                a[mt][1] = fu(Xs[(r + g + 8) * 36 + ks + tg]);
                a[mt][2] = fu(Xs[(r + g) * 36 + ks + tg + 4]);
                a[mt][3] = fu(Xs[(r + g + 8) * 36 + ks + tg + 4]);
            }
#pragma unroll
            for (int nt = 0; nt < 8; nt++) {
                uint32_t bb[2];
                int cn = wn * 64 + nt * 8 + g;
                bb[0] = fu(Ws[(ks + tg) * 132 + cn]);
                bb[1] = fu(Ws[(ks + tg + 4) * 132 + cn]);
                mma8(c[0][nt], a[0], bb);
                mma8(c[1][nt], a[1], bb);
            }
        }
        __syncthreads();
    }

    // Epilogue: bias, optional mask scale, store
#pragma unroll
    for (int mt = 0; mt < 2; mt++) {
        int r0 = m0 + wm * 32 + mt * 16 + g;
        int r1 = r0 + 8;
        float sc0 = 1.f, sc1 = 1.f;
        if (maskScale) {
            sc0 = maskScale[(size_t)r0 * TT];
            sc1 = maskScale[(size_t)r1 * TT];
        }
#pragma unroll
        for (int nt = 0; nt < 8; nt++) {
            int col = n0 + wn * 64 + nt * 8 + 2 * tg;
            float b0 = bias[col], b1 = bias[col + 1];
            float2 v0 = make_float2((c[mt][nt][0] + b0) * sc0, (c[mt][nt][1] + b1) * sc0);
            float2 v1 = make_float2((c[mt][nt][2] + b0) * sc1, (c[mt][nt][3] + b1) * sc1);
            *(float2*)&C[(size_t)r0 * 1024 + col] = v0;
            *(float2*)&C[(size_t)r1 * 1024 + col] = v1;
        }
    }
}

// ---------------- Flash attention ----------------
// Grid: (S/64, H, B). 128 threads = 4 warps; warp w owns q-rows [16w, 16w+16).
// Loops over T in chunks of 64: S = Q K^T * 1/8, online softmax, O += P V.
#define LDS_ 68   // padded stride: conflict-free fragment loads

__global__ void __launch_bounds__(128) flash_attn_kernel(
    const float* __restrict__ mask, const int* __restrict__ causal_p)
{
    extern __shared__ float sm[];
    float* Qs = sm;
    float* Ks = sm + 64 * LDS_;
    float* Vs = sm + 2 * 64 * LDS_;
    float* Ps = sm + 3 * 64 * LDS_;

    const int tid  = threadIdx.x;
    const int lane = tid & 31;
    const int warp = tid >> 5;
    const int g    = lane >> 2;
    const int tg   = lane & 3;
    const int s0   = blockIdx.x * 64;
    const int h    = blockIdx.y;
    const int b    = blockIdx.z;
    const int causal = causal_p[0];

    // Load Q tile [64 x 64] -> smem (tf32-rounded)
    const size_t qoff = ((size_t)b * SS + s0) * CHN + h * HD;
#pragma unroll
    for (int i = 0; i < 8; i++) {
        int idx = i * 128 + tid;
        int r = idx >> 4;
        int cc = (idx & 15) * 4;
        float4 v = *(const float4*)&g_Q[qoff + (size_t)r * CHN + cc];
        Qs[r * LDS_ + cc + 0] = f2tf_f(v.x);
        Qs[r * LDS_ + cc + 1] = f2tf_f(v.y);
        Qs[r * LDS_ + cc + 2] = f2tf_f(v.z);
        Qs[r * LDS_ + cc + 3] = f2tf_f(v.w);
    }
    __syncthreads();

    // Build persistent Q fragments (8 k-steps x 4 regs)
    const int r0w = warp * 16;
    uint32_t qa[8][4];
#pragma unroll
    for (int j = 0; j < 8; j++) {
        int k = j * 8;
        qa[j][0] = fu(Qs[(r0w + g) * LDS_ + k + tg]);
        qa[j][1] = fu(Qs[(r0w + g + 8) * LDS_ + k + tg]);
        qa[j][2] = fu(Qs[(r0w + g) * LDS_ + k + tg + 4]);
        qa[j][3] = fu(Qs[(r0w + g + 8) * LDS_ + k + tg + 4]);
    }

    float o[8][4];
#pragma unroll
    for (int nt = 0; nt < 8; nt++)
#pragma unroll
        for (int e = 0; e < 4; e++) o[nt][e] = 0.f;
    float m0 = -1e30f, m1 = -1e30f, l0 = 0.f, l1 = 0.f;

    const float* mb = mask + (size_t)b * SS * TT;
    const int rg0 = s0 + r0w + g;       // global q-row for c0/c1
    const int rg1 = rg0 + 8;            // global q-row for c2/c3

    for (int t0 = 0; t0 < TT; t0 += 64) {
        __syncthreads();  // protect Ks/Vs/Ps from previous iteration readers

        // Load K,V chunk [64 x 64] (tf32-rounded)
        const size_t kvoff = ((size_t)b * TT + t0) * CHN + h * HD;
#pragma unroll
        for (int i = 0; i < 8; i++) {
            int idx = i * 128 + tid;
            int r = idx >> 4;
            int cc = (idx & 15) * 4;
            float4 kv = *(const float4*)&g_K[kvoff + (size_t)r * CHN + cc];
            Ks[r * LDS_ + cc + 0] = f2tf_f(kv.x);
            Ks[r * LDS_ + cc + 1] = f2tf_f(kv.y);
            Ks[r * LDS_ + cc + 2] = f2tf_f(kv.z);
            Ks[r * LDS_ + cc + 3] = f2tf_f(kv.w);
            float4 vv = *(const float4*)&g_V[kvoff + (size_t)r * CHN + cc];
            Vs[r * LDS_ + cc + 0] = f2tf_f(vv.x);
            Vs[r * LDS_ + cc + 1] = f2tf_f(vv.y);
            Vs[r * LDS_ + cc + 2] = f2tf_f(vv.z);
            Vs[r * LDS_ + cc + 3] = f2tf_f(vv.w);
        }
        __syncthreads();

        // S = Q K^T : warp computes its 16 rows x 64 cols
        float s[8][4];
#pragma unroll
        for (int nt = 0; nt < 8; nt++)
#pragma unroll
            for (int e = 0; e < 4; e++) s[nt][e] = 0.f;
#pragma unroll
        for (int ks = 0; ks < 8; ks++) {
#pragma unroll
            for (int nt = 0; nt < 8; nt++) {
                uint32_t bb[2];
                int cn = nt * 8 + g;
                bb[0] = fu(Ks[cn * LDS_ + ks * 8 + tg]);
                bb[1] = fu(Ks[cn * LDS_ + ks * 8 + tg + 4]);
                mma8(s[nt], qa[ks], bb);
            }
        }

        // Scale + mask (reference semantics)
#pragma unroll
        for (int nt = 0; nt < 8; nt++) {
#pragma unroll
            for (int e = 0; e < 2; e++) {
                int t = t0 + nt * 8 + 2 * tg + e;
                float v0 = s[nt][e] * 0.125f;
                float v1 = s[nt][2 + e] * 0.125f;
                if (!causal) {
                    if (mb[t] == 0.f) { v0 = -1e30f; v1 = -1e30f; }
                } else {
                    // masked iff (mask[b,s,t] + tri) == 0  =>  mask==0 && t<=s
                    if (mb[(size_t)rg0 * TT + t] == 0.f && t <= rg0) v0 = -1e30f;
                    if (mb[(size_t)rg1 * TT + t] == 0.f && t <= rg1) v1 = -1e30f;
                }
                s[nt][e] = v0;
                s[nt][2 + e] = v1;
            }
        }

        // Online softmax: row maxima (quad-lane butterfly)
        float rm0 = -1e30f, rm1 = -1e30f;
#pragma unroll
        for (int nt = 0; nt < 8; nt++) {
            rm0 = fmaxf(rm0, fmaxf(s[nt][0], s[nt][1]));
            rm1 = fmaxf(rm1, fmaxf(s[nt][2], s[nt][3]));
        }
        rm0 = fmaxf(rm0, __shfl_xor_sync(0xffffffffu, rm0, 1));
        rm0 = fmaxf(rm0, __shfl_xor_sync(0xffffffffu, rm0, 2));
        rm1 = fmaxf(rm1, __shfl_xor_sync(0xffffffffu, rm1, 1));
        rm1 = fmaxf(rm1, __shfl_xor_sync(0xffffffffu, rm1, 2));

        float mn0 = fmaxf(m0, rm0);
        float mn1 = fmaxf(m1, rm1);
        float a0 = __expf(m0 - mn0);
        float a1 = __expf(m1 - mn1);
        m0 = mn0; m1 = mn1;

        float ls0 = 0.f, ls1 = 0.f;
#pragma unroll
        for (int nt = 0; nt < 8; nt++) {
            float p00 = __expf(s[nt][0] - m0);
            float p01 = __expf(s[nt][1] - m0);
            float p10 = __expf(s[nt][2] - m1);
            float p11 = __expf(s[nt][3] - m1);
            ls0 += p00 + p01;
            ls1 += p10 + p11;
            // write P (tf32-rounded) for the PV mma
            int cbase = nt * 8 + 2 * tg;
            Ps[(r0w + g) * LDS_ + cbase]         = f2tf_f(p00);
            Ps[(r0w + g) * LDS_ + cbase + 1]     = f2tf_f(p01);
            Ps[(r0w + g + 8) * LDS_ + cbase]     = f2tf_f(p10);
            Ps[(r0w + g + 8) * LDS_ + cbase + 1] = f2tf_f(p11);
            // rescale O accumulators
            o[nt][0] *= a0; o[nt][1] *= a0;
            o[nt][2] *= a1; o[nt][3] *= a1;
        }
        ls0 += __shfl_xor_sync(0xffffffffu, ls0, 1);
        ls0 += __shfl_xor_sync(0xffffffffu, ls0, 2);
        ls1 += __shfl_xor_sync(0xffffffffu, ls1, 1);
        ls1 += __shfl_xor_sync(0xffffffffu, ls1, 2);
        l0 = l0 * a0 + ls0;
        l1 = l1 * a1 + ls1;

        __syncwarp();  // warp reads only its own Ps rows

        // O += P V
#pragma unroll
        for (int ks = 0; ks < 8; ks++) {
            uint32_t pa[4];
            pa[0] = fu(Ps[(r0w + g) * LDS_ + ks * 8 + tg]);
            pa[1] = fu(Ps[(r0w + g + 8) * LDS_ + ks * 8 + tg]);
            pa[2] = fu(Ps[(r0w + g) * LDS_ + ks * 8 + tg + 4]);
            pa[3] = fu(Ps[(r0w + g + 8) * LDS_ + ks * 8 + tg + 4]);
#pragma unroll
            for (int nt = 0; nt < 8; nt++) {
                uint32_t bb[2];
                int cn = nt * 8 + g;
                bb[0] = fu(Vs[(ks * 8 + tg) * LDS_ + cn]);
                bb[1] = fu(Vs[(ks * 8 + tg + 4) * LDS_ + cn]);
                mma8(o[nt], pa, bb);
            }
        }
    }

    // Normalize and write out
    float i0 = 1.f / l0;
    float i1 = 1.f / l1;
    const size_t obase = ((size_t)b * SS + s0 + r0w) * CHN + h * HD;
#pragma unroll
    for (int nt = 0; nt < 8; nt++) {
        int col = nt * 8 + 2 * tg;
        float2 v0 = make_float2(o[nt][0] * i0, o[nt][1] * i0);
        float2 v1 = make_float2(o[nt][2] * i1, o[nt][3] * i1);
        *(float2*)&g_A[obase + (size_t)g * CHN + col] = v0;
        *(float2*)&g_A[obase + (size_t)(g + 8) * CHN + col] = v1;
    }
}

// ---------------- launch ----------------
extern "C" void kernel_launch(void* const* d_in, const int* in_sizes, int n_in,
                              void* d_out, int out_size)
{
    const float* query = (const float*)d_in[0];
    const float* key   = (const float*)d_in[1];
    const float* value = (const float*)d_in[2];
    const float* mask  = (const float*)d_in[3];
    const float* Wq    = (const float*)d_in[4];
    const float* bq    = (const float*)d_in[5];
    const float* Wk    = (const float*)d_in[6];
    const float* bk    = (const float*)d_in[7];
    const float* Wv    = (const float*)d_in[8];
    const float* bv    = (const float*)d_in[9];
    const float* Wo    = (const float*)d_in[10];
    const float* bo    = (const float*)d_in[11];
    const int*   causal = (const int*)d_in[12];
    float* out = (float*)d_out;

    float *Qp, *Kp, *Vp, *Ap;
    cudaGetSymbolAddress((void**)&Qp, g_Q);
    cudaGetSymbolAddress((void**)&Kp, g_K);
    cudaGetSymbolAddress((void**)&Vp, g_V);
    cudaGetSymbolAddress((void**)&Ap, g_A);

    dim3 ggrid(8, 32);   // N/128, M/128
    gemm_bias_kernel<<<ggrid, 256>>>(query, Wq, bq, Qp, nullptr);
    gemm_bias_kernel<<<ggrid, 256>>>(key,   Wk, bk, Kp, nullptr);
    gemm_bias_kernel<<<ggrid, 256>>>(value, Wv, bv, Vp, nullptr);

    const int fsmem = 4 * 64 * LDS_ * (int)sizeof(float);  // 69632 B
    cudaFuncSetAttribute(flash_attn_kernel,
                         cudaFuncAttributeMaxDynamicSharedMemorySize, fsmem);
    flash_attn_kernel<<<dim3(SS / 64, NH, BB), 128, fsmem>>>(mask, causal);

    gemm_bias_kernel<<<ggrid, 256>>>(Ap, Wo, bo, out, mask);
}

// round 4
// speedup vs baseline: 1.2436x; 1.2436x over previous
#include <cuda_runtime.h>
#include <cstdint>

// Problem constants
#define BB   2
#define SS   2048
#define TT   2048
#define CHN  1024
#define NH   16
#define HD   64
#define MM   (BB * SS)   // 4096 rows

// Scratch (device globals: allocation-free rule)
__device__ float g_Q[(size_t)MM * CHN];
__device__ float g_K[(size_t)MM * CHN];
__device__ float g_V[(size_t)MM * CHN];
__device__ float g_A[(size_t)MM * CHN];

// ---------------- helpers ----------------
__device__ __forceinline__ uint32_t f2tf(float x) {
    uint32_t u;
    asm("cvt.rna.tf32.f32 %0, %1;\n" : "=r"(u) : "f"(x));
    return u;
}
__device__ __forceinline__ float f2tf_f(float x) {
    return __uint_as_float(f2tf(x));
}
__device__ __forceinline__ uint32_t fu(float x) { return __float_as_uint(x); }

// D(16x8) += A(16x8, tf32, row) * B(8x8, tf32, col)
__device__ __forceinline__ void mma8(float c[4], const uint32_t a[4], const uint32_t b[2]) {
    asm volatile(
        "mma.sync.aligned.m16n8k8.row.col.f32.tf32.tf32.f32 "
        "{%0,%1,%2,%3}, {%4,%5,%6,%7}, {%8,%9}, {%0,%1,%2,%3};\n"
        : "+f"(c[0]), "+f"(c[1]), "+f"(c[2]), "+f"(c[3])
        : "r"(a[0]), "r"(a[1]), "r"(a[2]), "r"(a[3]), "r"(b[0]), "r"(b[1]));
}

// ---------------- GEMM: C[4096,1024] = X[4096,1024] @ W[1024,1024] + bias ----------------
// Register-prefetch double buffering (plain LDG/STS, single static smem buffer).
// BM=128, BN=128, BK=32, 256 threads (8 warps = 4m x 2n), warp tile 32x64.
__global__ void __launch_bounds__(256, 2) gemm_bias_kernel(
    const float* __restrict__ X, const float* __restrict__ W,
    const float* __restrict__ bias, float* __restrict__ C,
    const float* __restrict__ maskScale)
{
    __shared__ float Xs[128 * 36];   // [row][k], stride 36 -> conflict-free frags
    __shared__ float Ws[32 * 132];   // [k][col], stride 132 -> conflict-free frags

    const int tid  = threadIdx.x;
    const int lane = tid & 31;
    const int warp = tid >> 5;
    const int g    = lane >> 2;
    const int tg   = lane & 3;
    const int wm   = warp >> 1;   // 0..3
    const int wn   = warp & 1;    // 0..1
    const int m0   = blockIdx.y * 128;
    const int n0   = blockIdx.x * 128;

    // Per-thread prefetch registers: 4 float4 for X tile, 4 float4 for W tile
    float4 px[4], pw[4];

    auto ldg_tile = [&](int kt) {
#pragma unroll
        for (int i = 0; i < 4; i++) {
            int idx = i * 256 + tid;
            int xr = idx >> 3,  xc = (idx & 7) * 4;    // X: 128 rows x 8 float4
            int wr = idx >> 5,  wc = (idx & 31) * 4;   // W: 32 rows x 32 float4
            px[i] = *(const float4*)&X[(size_t)(m0 + xr) * 1024 + kt + xc];
            pw[i] = *(const float4*)&W[(size_t)(kt + wr) * 1024 + n0 + wc];
        }
    };
    auto sts_tile = [&]() {
#pragma unroll
        for (int i = 0; i < 4; i++) {
            int idx = i * 256 + tid;
            int xr = idx >> 3,  xc = (idx & 7) * 4;
            int wr = idx >> 5,  wc = (idx & 31) * 4;
            Xs[xr * 36 + xc + 0] = f2tf_f(px[i].x);
            Xs[xr * 36 + xc + 1] = f2tf_f(px[i].y);
            Xs[xr * 36 + xc + 2] = f2tf_f(px[i].z);
            Xs[xr * 36 + xc + 3] = f2tf_f(px[i].w);
            Ws[wr * 132 + wc + 0] = f2tf_f(pw[i].x);
            Ws[wr * 132 + wc + 1] = f2tf_f(pw[i].y);
            Ws[wr * 132 + wc + 2] = f2tf_f(pw[i].z);
            Ws[wr * 132 + wc + 3] = f2tf_f(pw[i].w);
        }
    };

    float c[2][8][4];
#pragma unroll
    for (int mt = 0; mt < 2; mt++)
#pragma unroll
        for (int nt = 0; nt < 8; nt++)
#pragma unroll
            for (int e = 0; e < 4; e++) c[mt][nt][e] = 0.f;

    ldg_tile(0);
    sts_tile();
    __syncthreads();

    for (int kt = 0; kt < 32; kt++) {
        // Prefetch next K-tile into registers (consumed after the compute phase)
        if (kt + 1 < 32) ldg_tile((kt + 1) * 32);

#pragma unroll
        for (int ks = 0; ks < 32; ks += 8) {
            uint32_t a[2][4];
#pragma unroll
            for (int mt = 0; mt < 2; mt++) {
                int r = wm * 32 + mt * 16;
                a[mt][0] = fu(Xs[(r + g) * 36 + ks + tg]);
                a[mt][1] = fu(Xs[(r + g + 8) * 36 + ks + tg]);
                a[mt][2] = fu(Xs[(r + g) * 36 + ks + tg + 4]);
                a[mt][3] = fu(Xs[(r + g + 8) * 36 + ks + tg + 4]);
            }
#pragma unroll
            for (int nt = 0; nt < 8; nt++) {
                uint32_t bb[2];
                int cn = wn * 64 + nt * 8 + g;
                bb[0] = fu(Ws[(ks + tg) * 132 + cn]);
                bb[1] = fu(Ws[(ks + tg + 4) * 132 + cn]);
                mma8(c[0][nt], a[0], bb);
                mma8(c[1][nt], a[1], bb);
            }
        }
        __syncthreads();                 // all warps done reading this tile
        if (kt + 1 < 32) {
            sts_tile();                  // overwrite with prefetched tile
            __syncthreads();
        }
    }

    // Epilogue: bias, optional mask scale, store
#pragma unroll
    for (int mt = 0; mt < 2; mt++) {
        int r0 = m0 + wm * 32 + mt * 16 + g;
        int r1 = r0 + 8;
        float sc0 = 1.f, sc1 = 1.f;
        if (maskScale) {
            sc0 = maskScale[(size_t)r0 * TT];
            sc1 = maskScale[(size_t)r1 * TT];
        }
#pragma unroll
        for (int nt = 0; nt < 8; nt++) {
            int col = n0 + wn * 64 + nt * 8 + 2 * tg;
            float b0 = bias[col], b1 = bias[col + 1];
            float2 v0 = make_float2((c[mt][nt][0] + b0) * sc0, (c[mt][nt][1] + b1) * sc0);
            float2 v1 = make_float2((c[mt][nt][2] + b0) * sc1, (c[mt][nt][3] + b1) * sc1);
            *(float2*)&C[(size_t)r0 * 1024 + col] = v0;
            *(float2*)&C[(size_t)r1 * 1024 + col] = v1;
        }
    }
}

// ---------------- Flash attention v2 (no cp.async) ----------------
// Grid: (S/128, H, B). 128 threads = 4 warps; warp w owns q-rows [32w, 32w+32)
// as 2 m-tiles of 16 -> each K/V B-fragment feeds 2 mmas.
// T chunks of 64, synchronous K/V smem fill (R1-proven pattern).
// P round-trips through the Q smem region (Q frags are register-persistent;
// each warp touches only its own 32 rows, guarded by __syncwarp).
#define LDS_  68      // padded stride: conflict-free fragment loads
#define FCH   64      // t-chunk
#define NCH   (TT / FCH)   // 32 chunks

__global__ void __launch_bounds__(128) flash_attn_kernel(
    const float* __restrict__ mask, const int* __restrict__ causal_p)
{
    extern __shared__ float sm[];
    float* Qs = sm;                     // 128*LDS_ ; reused as Ps after frag build
    float* Ks = sm + 128 * LDS_;        // 64*LDS_
    float* Vs = sm + 192 * LDS_;        // 64*LDS_

    const int tid  = threadIdx.x;
    const int lane = tid & 31;
    const int warp = tid >> 5;
    const int g    = lane >> 2;
    const int tg   = lane & 3;
    const int s0   = blockIdx.x * 128;
    const int h    = blockIdx.y;
    const int b    = blockIdx.z;
    const int causal = causal_p[0];

    // Load Q tile [128 x 64] -> smem (tf32-rounded)
    const size_t qoff = ((size_t)b * SS + s0) * CHN + h * HD;
#pragma unroll
    for (int i = 0; i < 16; i++) {
        int idx = i * 128 + tid;
        int r = idx >> 4, cc = (idx & 15) * 4;
        float4 v = *(const float4*)&g_Q[qoff + (size_t)r * CHN + cc];
        Qs[r * LDS_ + cc + 0] = f2tf_f(v.x);
        Qs[r * LDS_ + cc + 1] = f2tf_f(v.y);
        Qs[r * LDS_ + cc + 2] = f2tf_f(v.z);
        Qs[r * LDS_ + cc + 3] = f2tf_f(v.w);
    }
    __syncthreads();

    // Persistent Q fragments: 2 m-tiles x 8 k-steps x 4 regs
    uint32_t qa[2][8][4];
#pragma unroll
    for (int mt = 0; mt < 2; mt++) {
        int rb = warp * 32 + mt * 16;
#pragma unroll
        for (int j = 0; j < 8; j++) {
            int k = j * 8;
            qa[mt][j][0] = fu(Qs[(rb + g) * LDS_ + k + tg]);
            qa[mt][j][1] = fu(Qs[(rb + g + 8) * LDS_ + k + tg]);
            qa[mt][j][2] = fu(Qs[(rb + g) * LDS_ + k + tg + 4]);
            qa[mt][j][3] = fu(Qs[(rb + g + 8) * LDS_ + k + tg + 4]);
        }
    }

    float o[2][8][4];
#pragma unroll
    for (int mt = 0; mt < 2; mt++)
#pragma unroll
        for (int nt = 0; nt < 8; nt++)
#pragma unroll
            for (int e = 0; e < 4; e++) o[mt][nt][e] = 0.f;
    float mr[2][2] = {{-1e30f, -1e30f}, {-1e30f, -1e30f}};
    float lr[2][2] = {{0.f, 0.f}, {0.f, 0.f}};

    const float* mb = mask + (size_t)b * SS * TT;

    for (int ic = 0; ic < NCH; ic++) {
        const int t0 = ic * FCH;
        __syncthreads();   // all warps done reading Ks/Vs from previous chunk

        // Load K,V chunk [64 x 64] (tf32-rounded)
        const size_t kvoff = ((size_t)b * TT + t0) * CHN + h * HD;
#pragma unroll
        for (int i = 0; i < 8; i++) {
            int idx = i * 128 + tid;
            int r = idx >> 4, cc = (idx & 15) * 4;
            float4 kv = *(const float4*)&g_K[kvoff + (size_t)r * CHN + cc];
            float4 vv = *(const float4*)&g_V[kvoff + (size_t)r * CHN + cc];
            Ks[r * LDS_ + cc + 0] = f2tf_f(kv.x);
            Ks[r * LDS_ + cc + 1] = f2tf_f(kv.y);
            Ks[r * LDS_ + cc + 2] = f2tf_f(kv.z);
            Ks[r * LDS_ + cc + 3] = f2tf_f(kv.w);
            Vs[r * LDS_ + cc + 0] = f2tf_f(vv.x);
            Vs[r * LDS_ + cc + 1] = f2tf_f(vv.y);
            Vs[r * LDS_ + cc + 2] = f2tf_f(vv.z);
            Vs[r * LDS_ + cc + 3] = f2tf_f(vv.w);
        }
        __syncthreads();

        // S = Q K^T : each B frag feeds both m-tiles
        float s[2][8][4];
#pragma unroll
        for (int mt = 0; mt < 2; mt++)
#pragma unroll
            for (int nt = 0; nt < 8; nt++)
#pragma unroll
                for (int e = 0; e < 4; e++) s[mt][nt][e] = 0.f;
#pragma unroll
        for (int ks = 0; ks < 8; ks++) {
#pragma unroll
            for (int nt = 0; nt < 8; nt++) {
                uint32_t bb[2];
                int cn = nt * 8 + g;
                bb[0] = fu(Ks[cn * LDS_ + ks * 8 + tg]);
                bb[1] = fu(Ks[cn * LDS_ + ks * 8 + tg + 4]);
                mma8(s[0][nt], qa[0][ks], bb);
                mma8(s[1][nt], qa[1][ks], bb);
            }
        }

        // Scale + mask (reference semantics)
#pragma unroll
        for (int mt = 0; mt < 2; mt++) {
            int rg0 = s0 + warp * 32 + mt * 16 + g;
            int rg1 = rg0 + 8;
#pragma unroll
            for (int nt = 0; nt < 8; nt++) {
#pragma unroll
                for (int e = 0; e < 2; e++) {
                    int t = t0 + nt * 8 + 2 * tg + e;
                    float v0 = s[mt][nt][e] * 0.125f;
                    float v1 = s[mt][nt][2 + e] * 0.125f;
                    if (!causal) {
                        if (mb[t] == 0.f) { v0 = -1e30f; v1 = -1e30f; }
                    } else {
                        if (mb[(size_t)rg0 * TT + t] == 0.f && t <= rg0) v0 = -1e30f;
                        if (mb[(size_t)rg1 * TT + t] == 0.f && t <= rg1) v1 = -1e30f;
                    }
                    s[mt][nt][e] = v0;
                    s[mt][nt][2 + e] = v1;
                }
            }
        }

        // Online softmax per m-tile; write P into Qs region (own rows only)
#pragma unroll
        for (int mt = 0; mt < 2; mt++) {
            float rm0 = -1e30f, rm1 = -1e30f;
#pragma unroll
            for (int nt = 0; nt < 8; nt++) {
                rm0 = fmaxf(rm0, fmaxf(s[mt][nt][0], s[mt][nt][1]));
                rm1 = fmaxf(rm1, fmaxf(s[mt][nt][2], s[mt][nt][3]));
            }
            rm0 = fmaxf(rm0, __shfl_xor_sync(0xffffffffu, rm0, 1));
            rm0 = fmaxf(rm0, __shfl_xor_sync(0xffffffffu, rm0, 2));
            rm1 = fmaxf(rm1, __shfl_xor_sync(0xffffffffu, rm1, 1));
            rm1 = fmaxf(rm1, __shfl_xor_sync(0xffffffffu, rm1, 2));

            float mn0 = fmaxf(mr[mt][0], rm0);
            float mn1 = fmaxf(mr[mt][1], rm1);
            float a0 = __expf(mr[mt][0] - mn0);
            float a1 = __expf(mr[mt][1] - mn1);
            mr[mt][0] = mn0; mr[mt][1] = mn1;

            int rb = warp * 32 + mt * 16;
            float ls0 = 0.f, ls1 = 0.f;
#pragma unroll
            for (int nt = 0; nt < 8; nt++) {
                float p00 = __expf(s[mt][nt][0] - mn0);
                float p01 = __expf(s[mt][nt][1] - mn0);
                float p10 = __expf(s[mt][nt][2] - mn1);
                float p11 = __expf(s[mt][nt][3] - mn1);
                ls0 += p00 + p01;
                ls1 += p10 + p11;
                int cb = nt * 8 + 2 * tg;
                Qs[(rb + g) * LDS_ + cb]         = f2tf_f(p00);
                Qs[(rb + g) * LDS_ + cb + 1]     = f2tf_f(p01);
                Qs[(rb + g + 8) * LDS_ + cb]     = f2tf_f(p10);
                Qs[(rb + g + 8) * LDS_ + cb + 1] = f2tf_f(p11);
                o[mt][nt][0] *= a0; o[mt][nt][1] *= a0;
                o[mt][nt][2] *= a1; o[mt][nt][3] *= a1;
            }
            ls0 += __shfl_xor_sync(0xffffffffu, ls0, 1);
            ls0 += __shfl_xor_sync(0xffffffffu, ls0, 2);
            ls1 += __shfl_xor_sync(0xffffffffu, ls1, 1);
            ls1 += __shfl_xor_sync(0xffffffffu, ls1, 2);
            lr[mt][0] = lr[mt][0] * a0 + ls0;
            lr[mt][1] = lr[mt][1] * a1 + ls1;
        }
        __syncwarp();   // warp reads only its own P rows

        // O += P V (each V frag feeds both m-tiles)
#pragma unroll
        for (int ks = 0; ks < 8; ks++) {
            uint32_t pa[2][4];
#pragma unroll
            for (int mt = 0; mt < 2; mt++) {
                int rb = warp * 32 + mt * 16;
                pa[mt][0] = fu(Qs[(rb + g) * LDS_ + ks * 8 + tg]);
                pa[mt][1] = fu(Qs[(rb + g + 8) * LDS_ + ks * 8 + tg]);
                pa[mt][2] = fu(Qs[(rb + g) * LDS_ + ks * 8 + tg + 4]);
                pa[mt][3] = fu(Qs[(rb + g + 8) * LDS_ + ks * 8 + tg + 4]);
            }
#pragma unroll
            for (int nt = 0; nt < 8; nt++) {
                uint32_t bb[2];
                int cn = nt * 8 + g;
                bb[0] = fu(Vs[(ks * 8 + tg) * LDS_ + cn]);
                bb[1] = fu(Vs[(ks * 8 + tg + 4) * LDS_ + cn]);
                mma8(o[0][nt], pa[0], bb);
                mma8(o[1][nt], pa[1], bb);
            }
        }
    }

    // Normalize and write out
#pragma unroll
    for (int mt = 0; mt < 2; mt++) {
        float i0 = 1.f / lr[mt][0];
        float i1 = 1.f / lr[mt][1];
        const size_t ob = ((size_t)b * SS + s0 + warp * 32 + mt * 16) * CHN + h * HD;
#pragma unroll
        for (int nt = 0; nt < 8; nt++) {
            int col = nt * 8 + 2 * tg;
            float2 v0 = make_float2(o[mt][nt][0] * i0, o[mt][nt][1] * i0);
            float2 v1 = make_float2(o[mt][nt][2] * i1, o[mt][nt][3] * i1);
            *(float2*)&g_A[ob + (size_t)g * CHN + col] = v0;
            *(float2*)&g_A[ob + (size_t)(g + 8) * CHN + col] = v1;
        }
    }
}

// ---------------- launch ----------------
extern "C" void kernel_launch(void* const* d_in, const int* in_sizes, int n_in,
                              void* d_out, int out_size)
{
    const float* query = (const float*)d_in[0];
    const float* key   = (const float*)d_in[1];
    const float* value = (const float*)d_in[2];
    const float* mask  = (const float*)d_in[3];
    const float* Wq    = (const float*)d_in[4];
    const float* bq    = (const float*)d_in[5];
    const float* Wk    = (const float*)d_in[6];
    const float* bk    = (const float*)d_in[7];
    const float* Wv    = (const float*)d_in[8];
    const float* bv    = (const float*)d_in[9];
    const float* Wo    = (const float*)d_in[10];
    const float* bo    = (const float*)d_in[11];
    const int*   causal = (const int*)d_in[12];
    float* out = (float*)d_out;

    float *Qp, *Kp, *Vp, *Ap;
    cudaGetSymbolAddress((void**)&Qp, g_Q);
    cudaGetSymbolAddress((void**)&Kp, g_K);
    cudaGetSymbolAddress((void**)&Vp, g_V);
    cudaGetSymbolAddress((void**)&Ap, g_A);

    dim3 ggrid(8, 32);   // N/128, M/128
    gemm_bias_kernel<<<ggrid, 256>>>(query, Wq, bq, Qp, nullptr);
    gemm_bias_kernel<<<ggrid, 256>>>(key,   Wk, bk, Kp, nullptr);
    gemm_bias_kernel<<<ggrid, 256>>>(value, Wv, bv, Vp, nullptr);

    const int fsmem = 256 * LDS_ * (int)sizeof(float);   // 69,632 B (same as R1)
    cudaFuncSetAttribute(flash_attn_kernel,
                         cudaFuncAttributeMaxDynamicSharedMemorySize, fsmem);
    flash_attn_kernel<<<dim3(SS / 128, NH, BB), 128, fsmem>>>(mask, causal);

    gemm_bias_kernel<<<ggrid, 256>>>(Ap, Wo, bo, out, mask);
}

// round 5
// speedup vs baseline: 1.2559x; 1.0099x over previous
#include <cuda_runtime.h>
#include <cstdint>

// Problem constants
#define BB   2
#define SS   2048
#define TT   2048
#define CHN  1024
#define NH   16
#define HD   64
#define MM   (BB * SS)   // 4096 rows

// Scratch (device globals: allocation-free rule)
__device__ float g_Q[(size_t)MM * CHN];
__device__ float g_K[(size_t)MM * CHN];
__device__ float g_V[(size_t)MM * CHN];
__device__ float g_A[(size_t)MM * CHN];

// ---------------- helpers ----------------
__device__ __forceinline__ uint32_t f2tf(float x) {
    uint32_t u;
    asm("cvt.rna.tf32.f32 %0, %1;\n" : "=r"(u) : "f"(x));
    return u;
}
__device__ __forceinline__ float f2tf_f(float x) {
    return __uint_as_float(f2tf(x));
}
__device__ __forceinline__ uint32_t fu(float x) { return __float_as_uint(x); }

__device__ __forceinline__ float4 tf4(float4 v) {
    return make_float4(f2tf_f(v.x), f2tf_f(v.y), f2tf_f(v.z), f2tf_f(v.w));
}

// D(16x8) += A(16x8, tf32, row) * B(8x8, tf32, col)
__device__ __forceinline__ void mma8(float c[4], const uint32_t a[4], const uint32_t b[2]) {
    asm volatile(
        "mma.sync.aligned.m16n8k8.row.col.f32.tf32.tf32.f32 "
        "{%0,%1,%2,%3}, {%4,%5,%6,%7}, {%8,%9}, {%0,%1,%2,%3};\n"
        : "+f"(c[0]), "+f"(c[1]), "+f"(c[2]), "+f"(c[3])
        : "r"(a[0]), "r"(a[1]), "r"(a[2]), "r"(a[3]), "r"(b[0]), "r"(b[1]));
}

// ---------------- GEMM: C[4096,1024] = X[4096,1024] @ W[1024,1024] + bias ----------------
// Double-buffered smem (1 barrier/ktile) + register prefetch + STS.128 stores.
// BM=128, BN=128, BK=32, 256 threads (8 warps = 4m x 2n), warp tile 32x64.
#define GXF  (128 * 36)          // X stage floats
#define GWF  (32 * 132)          // W stage floats
#define GSTG (GXF + GWF)         // 8832 floats per stage

__global__ void __launch_bounds__(256, 2) gemm_bias_kernel(
    const float* __restrict__ X, const float* __restrict__ W,
    const float* __restrict__ bias, float* __restrict__ C,
    const float* __restrict__ maskScale)
{
    extern __shared__ float gsm[];   // 2 stages

    const int tid  = threadIdx.x;
    const int lane = tid & 31;
    const int warp = tid >> 5;
    const int g    = lane >> 2;
    const int tg   = lane & 3;
    const int wm   = warp >> 1;   // 0..3
    const int wn   = warp & 1;    // 0..1
    const int m0   = blockIdx.y * 128;
    const int n0   = blockIdx.x * 128;

    // Per-thread prefetch registers: 4 float4 X, 4 float4 W
    float4 px[4], pw[4];

    auto ldg_tile = [&](int kt) {
#pragma unroll
        for (int i = 0; i < 4; i++) {
            int idx = i * 256 + tid;
            int xr = idx >> 3,  xc = (idx & 7) * 4;    // X: 128 rows x 8 float4
            int wr = idx >> 5,  wc = (idx & 31) * 4;   // W: 32 rows x 32 float4
            px[i] = *(const float4*)&X[(size_t)(m0 + xr) * 1024 + kt + xc];
            pw[i] = *(const float4*)&W[(size_t)(kt + wr) * 1024 + n0 + wc];
        }
    };
    auto sts_tile = [&](int st) {
        float* Xs = gsm + st * GSTG;
        float* Ws = Xs + GXF;
#pragma unroll
        for (int i = 0; i < 4; i++) {
            int idx = i * 256 + tid;
            int xr = idx >> 3,  xc = (idx & 7) * 4;
            int wr = idx >> 5,  wc = (idx & 31) * 4;
            *(float4*)&Xs[xr * 36 + xc]  = tf4(px[i]);   // 36,132 strides: 16B aligned
            *(float4*)&Ws[wr * 132 + wc] = tf4(pw[i]);
        }
    };

    float c[2][8][4];
#pragma unroll
    for (int mt = 0; mt < 2; mt++)
#pragma unroll
        for (int nt = 0; nt < 8; nt++)
#pragma unroll
            for (int e = 0; e < 4; e++) c[mt][nt][e] = 0.f;

    ldg_tile(0);
    sts_tile(0);
    __syncthreads();

    for (int kt = 0; kt < 32; kt++) {
        // Prefetch next tile into registers early (hide global latency)
        if (kt + 1 < 32) ldg_tile((kt + 1) * 32);

        const float* Xs = gsm + (kt & 1) * GSTG;
        const float* Ws = Xs + GXF;

#pragma unroll
        for (int ks = 0; ks < 32; ks += 8) {
            uint32_t a[2][4];
#pragma unroll
            for (int mt = 0; mt < 2; mt++) {
                int r = wm * 32 + mt * 16;
                a[mt][0] = fu(Xs[(r + g) * 36 + ks + tg]);
                a[mt][1] = fu(Xs[(r + g + 8) * 36 + ks + tg]);
                a[mt][2] = fu(Xs[(r + g) * 36 + ks + tg + 4]);
                a[mt][3] = fu(Xs[(r + g + 8) * 36 + ks + tg + 4]);
            }
#pragma unroll
            for (int nt = 0; nt < 8; nt++) {
                uint32_t bb[2];
                int cn = wn * 64 + nt * 8 + g;
                bb[0] = fu(Ws[(ks + tg) * 132 + cn]);
                bb[1] = fu(Ws[(ks + tg + 4) * 132 + cn]);
                mma8(c[0][nt], a[0], bb);
                mma8(c[1][nt], a[1], bb);
            }
        }

        // Store prefetched tile into the OTHER buffer; its previous readers all
        // finished at the barrier that ended iteration kt-1.
        if (kt + 1 < 32) sts_tile((kt + 1) & 1);
        __syncthreads();   // publish next buffer / guard current buffer reuse
    }

    // Epilogue: bias, optional mask scale, store
#pragma unroll
    for (int mt = 0; mt < 2; mt++) {
        int r0 = m0 + wm * 32 + mt * 16 + g;
        int r1 = r0 + 8;
        float sc0 = 1.f, sc1 = 1.f;
        if (maskScale) {
            sc0 = maskScale[(size_t)r0 * TT];
            sc1 = maskScale[(size_t)r1 * TT];
        }
#pragma unroll
        for (int nt = 0; nt < 8; nt++) {
            int col = n0 + wn * 64 + nt * 8 + 2 * tg;
            float b0 = bias[col], b1 = bias[col + 1];
            float2 v0 = make_float2((c[mt][nt][0] + b0) * sc0, (c[mt][nt][1] + b1) * sc0);
            float2 v1 = make_float2((c[mt][nt][2] + b0) * sc1, (c[mt][nt][3] + b1) * sc1);
            *(float2*)&C[(size_t)r0 * 1024 + col] = v0;
            *(float2*)&C[(size_t)r1 * 1024 + col] = v1;
        }
    }
}

// ---------------- Flash attention v3 ----------------
// Grid: (S/128, H, B). 128 threads = 4 warps; warp w owns q-rows [32w, 32w+32)
// as 2 m-tiles of 16 -> each K/V B-fragment feeds 2 mmas.
// T chunks of 64; synchronous, vectorized K/V smem fill.
// P round-trips through the Q smem region (Q frags are register-persistent;
// each warp touches only its own 32 rows, guarded by __syncwarp).
#define LDS_  68      // padded stride: conflict-free fragment loads
#define FCH   64      // t-chunk
#define NCH   (TT / FCH)   // 32 chunks

__global__ void __launch_bounds__(128) flash_attn_kernel(
    const float* __restrict__ mask, const int* __restrict__ causal_p)
{
    extern __shared__ float sm[];
    float* Qs = sm;                     // 128*LDS_ ; reused as Ps after frag build
    float* Ks = sm + 128 * LDS_;        // 64*LDS_
    float* Vs = sm + 192 * LDS_;        // 64*LDS_

    const int tid  = threadIdx.x;
    const int lane = tid & 31;
    const int warp = tid >> 5;
    const int g    = lane >> 2;
    const int tg   = lane & 3;
    const int s0   = blockIdx.x * 128;
    const int h    = blockIdx.y;
    const int b    = blockIdx.z;
    const int causal = causal_p[0];

    // Load Q tile [128 x 64] -> smem (tf32-rounded, vectorized)
    const size_t qoff = ((size_t)b * SS + s0) * CHN + h * HD;
#pragma unroll
    for (int i = 0; i < 16; i++) {
        int idx = i * 128 + tid;
        int r = idx >> 4, cc = (idx & 15) * 4;
        float4 v = *(const float4*)&g_Q[qoff + (size_t)r * CHN + cc];
        *(float4*)&Qs[r * LDS_ + cc] = tf4(v);
    }
    __syncthreads();

    // Persistent Q fragments: 2 m-tiles x 8 k-steps x 4 regs
    uint32_t qa[2][8][4];
#pragma unroll
    for (int mt = 0; mt < 2; mt++) {
        int rb = warp * 32 + mt * 16;
#pragma unroll
        for (int j = 0; j < 8; j++) {
            int k = j * 8;
            qa[mt][j][0] = fu(Qs[(rb + g) * LDS_ + k + tg]);
            qa[mt][j][1] = fu(Qs[(rb + g + 8) * LDS_ + k + tg]);
            qa[mt][j][2] = fu(Qs[(rb + g) * LDS_ + k + tg + 4]);
            qa[mt][j][3] = fu(Qs[(rb + g + 8) * LDS_ + k + tg + 4]);
        }
    }

    float o[2][8][4];
#pragma unroll
    for (int mt = 0; mt < 2; mt++)
#pragma unroll
        for (int nt = 0; nt < 8; nt++)
#pragma unroll
            for (int e = 0; e < 4; e++) o[mt][nt][e] = 0.f;
    float mr[2][2] = {{-1e30f, -1e30f}, {-1e30f, -1e30f}};
    float lr[2][2] = {{0.f, 0.f}, {0.f, 0.f}};

    const float* mb = mask + (size_t)b * SS * TT;

    for (int ic = 0; ic < NCH; ic++) {
        const int t0 = ic * FCH;
        __syncthreads();   // all warps done reading Ks/Vs from previous chunk

        // Load K,V chunk [64 x 64] (convert in regs, STS.128)
        const size_t kvoff = ((size_t)b * TT + t0) * CHN + h * HD;
#pragma unroll
        for (int i = 0; i < 8; i++) {
            int idx = i * 128 + tid;
            int r = idx >> 4, cc = (idx & 15) * 4;
            float4 kv = *(const float4*)&g_K[kvoff + (size_t)r * CHN + cc];
            float4 vv = *(const float4*)&g_V[kvoff + (size_t)r * CHN + cc];
            *(float4*)&Ks[r * LDS_ + cc] = tf4(kv);
            *(float4*)&Vs[r * LDS_ + cc] = tf4(vv);
        }
        __syncthreads();

        // S = Q K^T : each B frag feeds both m-tiles
        float s[2][8][4];
#pragma unroll
        for (int mt = 0; mt < 2; mt++)
#pragma unroll
            for (int nt = 0; nt < 8; nt++)
#pragma unroll
                for (int e = 0; e < 4; e++) s[mt][nt][e] = 0.f;
#pragma unroll
        for (int ks = 0; ks < 8; ks++) {
#pragma unroll
            for (int nt = 0; nt < 8; nt++) {
                uint32_t bb[2];
                int cn = nt * 8 + g;
                bb[0] = fu(Ks[cn * LDS_ + ks * 8 + tg]);
                bb[1] = fu(Ks[cn * LDS_ + ks * 8 + tg + 4]);
                mma8(s[0][nt], qa[0][ks], bb);
                mma8(s[1][nt], qa[1][ks], bb);
            }
        }

        // Scale + mask (reference semantics).
        // Non-causal: mask flags depend only on t -> hoist out of mt loop.
        if (!causal) {
            bool mz[8][2];
#pragma unroll
            for (int nt = 0; nt < 8; nt++) {
#pragma unroll
                for (int e = 0; e < 2; e++)
                    mz[nt][e] = (mb[t0 + nt * 8 + 2 * tg + e] == 0.f);
            }
#pragma unroll
            for (int mt = 0; mt < 2; mt++)
#pragma unroll
                for (int nt = 0; nt < 8; nt++)
#pragma unroll
                    for (int e = 0; e < 2; e++) {
                        s[mt][nt][e]     = mz[nt][e] ? -1e30f : s[mt][nt][e] * 0.125f;
                        s[mt][nt][2 + e] = mz[nt][e] ? -1e30f : s[mt][nt][2 + e] * 0.125f;
                    }
        } else {
#pragma unroll
            for (int mt = 0; mt < 2; mt++) {
                int rg0 = s0 + warp * 32 + mt * 16 + g;
                int rg1 = rg0 + 8;
#pragma unroll
                for (int nt = 0; nt < 8; nt++) {
#pragma unroll
                    for (int e = 0; e < 2; e++) {
                        int t = t0 + nt * 8 + 2 * tg + e;
                        float v0 = s[mt][nt][e] * 0.125f;
                        float v1 = s[mt][nt][2 + e] * 0.125f;
                        // masked iff mask[b,s,t]==0 && t<=s  (mask + triu == 0)
                        if (mb[(size_t)rg0 * TT + t] == 0.f && t <= rg0) v0 = -1e30f;
                        if (mb[(size_t)rg1 * TT + t] == 0.f && t <= rg1) v1 = -1e30f;
                        s[mt][nt][e] = v0;
                        s[mt][nt][2 + e] = v1;
                    }
                }
            }
        }

        // Online softmax per m-tile; write P into Qs region (own rows only)
#pragma unroll
        for (int mt = 0; mt < 2; mt++) {
            float rm0 = -1e30f, rm1 = -1e30f;
#pragma unroll
            for (int nt = 0; nt < 8; nt++) {
                rm0 = fmaxf(rm0, fmaxf(s[mt][nt][0], s[mt][nt][1]));
                rm1 = fmaxf(rm1, fmaxf(s[mt][nt][2], s[mt][nt][3]));
            }
            rm0 = fmaxf(rm0, __shfl_xor_sync(0xffffffffu, rm0, 1));
            rm0 = fmaxf(rm0, __shfl_xor_sync(0xffffffffu, rm0, 2));
            rm1 = fmaxf(rm1, __shfl_xor_sync(0xffffffffu, rm1, 1));
            rm1 = fmaxf(rm1, __shfl_xor_sync(0xffffffffu, rm1, 2));

            float mn0 = fmaxf(mr[mt][0], rm0);
            float mn1 = fmaxf(mr[mt][1], rm1);
            float a0 = __expf(mr[mt][0] - mn0);
            float a1 = __expf(mr[mt][1] - mn1);
            mr[mt][0] = mn0; mr[mt][1] = mn1;

            int rb = warp * 32 + mt * 16;
            float ls0 = 0.f, ls1 = 0.f;
#pragma unroll
            for (int nt = 0; nt < 8; nt++) {
                float p00 = __expf(s[mt][nt][0] - mn0);
                float p01 = __expf(s[mt][nt][1] - mn0);
                float p10 = __expf(s[mt][nt][2] - mn1);
                float p11 = __expf(s[mt][nt][3] - mn1);
                ls0 += p00 + p01;
                ls1 += p10 + p11;
                int cb = nt * 8 + 2 * tg;
                *(float2*)&Qs[(rb + g) * LDS_ + cb] =
                    make_float2(f2tf_f(p00), f2tf_f(p01));
                *(float2*)&Qs[(rb + g + 8) * LDS_ + cb] =
                    make_float2(f2tf_f(p10), f2tf_f(p11));
                o[mt][nt][0] *= a0; o[mt][nt][1] *= a0;
                o[mt][nt][2] *= a1; o[mt][nt][3] *= a1;
            }
            ls0 += __shfl_xor_sync(0xffffffffu, ls0, 1);
            ls0 += __shfl_xor_sync(0xffffffffu, ls0, 2);
            ls1 += __shfl_xor_sync(0xffffffffu, ls1, 1);
            ls1 += __shfl_xor_sync(0xffffffffu, ls1, 2);
            lr[mt][0] = lr[mt][0] * a0 + ls0;
            lr[mt][1] = lr[mt][1] * a1 + ls1;
        }
        __syncwarp();   // warp reads only its own P rows

        // O += P V (each V frag feeds both m-tiles)
#pragma unroll
        for (int ks = 0; ks < 8; ks++) {
            uint32_t pa[2][4];
#pragma unroll
            for (int mt = 0; mt < 2; mt++) {
                int rb = warp * 32 + mt * 16;
                pa[mt][0] = fu(Qs[(rb + g) * LDS_ + ks * 8 + tg]);
                pa[mt][1] = fu(Qs[(rb + g + 8) * LDS_ + ks * 8 + tg]);
                pa[mt][2] = fu(Qs[(rb + g) * LDS_ + ks * 8 + tg + 4]);
                pa[mt][3] = fu(Qs[(rb + g + 8) * LDS_ + ks * 8 + tg + 4]);
            }
#pragma unroll
            for (int nt = 0; nt < 8; nt++) {
                uint32_t bb[2];
                int cn = nt * 8 + g;
                bb[0] = fu(Vs[(ks * 8 + tg) * LDS_ + cn]);
                bb[1] = fu(Vs[(ks * 8 + tg + 4) * LDS_ + cn]);
                mma8(o[0][nt], pa[0], bb);
                mma8(o[1][nt], pa[1], bb);
            }
        }
    }

    // Normalize and write out
#pragma unroll
    for (int mt = 0; mt < 2; mt++) {
        float i0 = 1.f / lr[mt][0];
        float i1 = 1.f / lr[mt][1];
        const size_t ob = ((size_t)b * SS + s0 + warp * 32 + mt * 16) * CHN + h * HD;
#pragma unroll
        for (int nt = 0; nt < 8; nt++) {
            int col = nt * 8 + 2 * tg;
            float2 v0 = make_float2(o[mt][nt][0] * i0, o[mt][nt][1] * i0);
            float2 v1 = make_float2(o[mt][nt][2] * i1, o[mt][nt][3] * i1);
            *(float2*)&g_A[ob + (size_t)g * CHN + col] = v0;
            *(float2*)&g_A[ob + (size_t)(g + 8) * CHN + col] = v1;
        }
    }
}

// ---------------- launch ----------------
extern "C" void kernel_launch(void* const* d_in, const int* in_sizes, int n_in,
                              void* d_out, int out_size)
{
    const float* query = (const float*)d_in[0];
    const float* key   = (const float*)d_in[1];
    const float* value = (const float*)d_in[2];
    const float* mask  = (const float*)d_in[3];
    const float* Wq    = (const float*)d_in[4];
    const float* bq    = (const float*)d_in[5];
    const float* Wk    = (const float*)d_in[6];
    const float* bk    = (const float*)d_in[7];
    const float* Wv    = (const float*)d_in[8];
    const float* bv    = (const float*)d_in[9];
    const float* Wo    = (const float*)d_in[10];
    const float* bo    = (const float*)d_in[11];
    const int*   causal = (const int*)d_in[12];
    float* out = (float*)d_out;

    float *Qp, *Kp, *Vp, *Ap;
    cudaGetSymbolAddress((void**)&Qp, g_Q);
    cudaGetSymbolAddress((void**)&Kp, g_K);
    cudaGetSymbolAddress((void**)&Vp, g_V);
    cudaGetSymbolAddress((void**)&Ap, g_A);

    const int gsmem = 2 * GSTG * (int)sizeof(float);   // 70,656 B
    cudaFuncSetAttribute(gemm_bias_kernel,
                         cudaFuncAttributeMaxDynamicSharedMemorySize, gsmem);

    dim3 ggrid(8, 32);   // N/128, M/128
    gemm_bias_kernel<<<ggrid, 256, gsmem>>>(query, Wq, bq, Qp, nullptr);
    gemm_bias_kernel<<<ggrid, 256, gsmem>>>(key,   Wk, bk, Kp, nullptr);
    gemm_bias_kernel<<<ggrid, 256, gsmem>>>(value, Wv, bv, Vp, nullptr);

    const int fsmem = 256 * LDS_ * (int)sizeof(float);   // 69,632 B
    cudaFuncSetAttribute(flash_attn_kernel,
                         cudaFuncAttributeMaxDynamicSharedMemorySize, fsmem);
    flash_attn_kernel<<<dim3(SS / 128, NH, BB), 128, fsmem>>>(mask, causal);

    gemm_bias_kernel<<<ggrid, 256, gsmem>>>(Ap, Wo, bo, out, mask);
}

// round 9
// speedup vs baseline: 1.3838x; 1.1018x over previous
#include <cuda_runtime.h>
#include <cstdint>

// Problem constants
#define BB   2
#define SS   2048
#define TT   2048
#define CHN  1024
#define NH   16
#define HD   64
#define MM   (BB * SS)   // 4096 rows

// Scratch (device globals: allocation-free rule)
__device__ float g_Q[(size_t)MM * CHN];
__device__ float g_K[(size_t)MM * CHN];
__device__ float g_V[(size_t)MM * CHN];
__device__ float g_A[(size_t)MM * CHN];

// ---------------- helpers ----------------
__device__ __forceinline__ uint32_t f2tf(float x) {
    uint32_t u;
    asm("cvt.rna.tf32.f32 %0, %1;\n" : "=r"(u) : "f"(x));
    return u;
}
__device__ __forceinline__ float f2tf_f(float x) {
    return __uint_as_float(f2tf(x));
}
__device__ __forceinline__ uint32_t fu(float x) { return __float_as_uint(x); }

__device__ __forceinline__ float4 tf4(float4 v) {
    return make_float4(f2tf_f(v.x), f2tf_f(v.y), f2tf_f(v.z), f2tf_f(v.w));
}

__device__ __forceinline__ uint32_t smem_u32(const void* p) {
    return (uint32_t)__cvta_generic_to_shared(p);
}

// D(16x8) += A(16x8, tf32, row) * B(8x8, tf32, col)
__device__ __forceinline__ void mma8(float c[4], const uint32_t a[4], const uint32_t b[2]) {
    asm volatile(
        "mma.sync.aligned.m16n8k8.row.col.f32.tf32.tf32.f32 "
        "{%0,%1,%2,%3}, {%4,%5,%6,%7}, {%8,%9}, {%0,%1,%2,%3};\n"
        : "+f"(c[0]), "+f"(c[1]), "+f"(c[2]), "+f"(c[3])
        : "r"(a[0]), "r"(a[1]), "r"(a[2]), "r"(a[3]), "r"(b[0]), "r"(b[1]));
}

// ldmatrix x4: 4 8x8-b16 matrices (= 8x4-tf32 blocks). Lane L of matrix j gets
// the 32-bit word at (row L/4, col L%4) -> exact tf32 mma fragment layout.
// Lanes 0-7 supply row addrs of matrix0, 8-15 matrix1, 16-23 matrix2, 24-31 matrix3.
__device__ __forceinline__ void ldsm_x4(uint32_t r[4], uint32_t saddr) {
    asm volatile("ldmatrix.sync.aligned.m8n8.x4.shared.b16 {%0,%1,%2,%3}, [%4];"
        : "=r"(r[0]), "=r"(r[1]), "=r"(r[2]), "=r"(r[3]) : "r"(saddr));
}

// ---------------- GEMM: C[4096,1024] = X @ W + bias ----------------
// BM=128, BN=128, BK=32, 256 threads (8 warps = 4m x 2n), warp tile 32x64.
// Double-buffered smem + register prefetch. Fragments via LDSM.
// Xs: [m][k] stride 36 (rows = 144B, 16B-aligned; LDSM conflict-free).
// Ws: [n][k] stride 36 (n-major so LDSM rows are k-contiguous).
#define GXF   (128 * 36)          // Xs floats
#define GWF   (128 * 36)          // Ws floats
#define GSTG  (GXF + GWF)         // 9216 floats per stage
#define GSTGB (GSTG * 4)

__global__ void __launch_bounds__(256, 2) gemm_bias_kernel(
    const float* __restrict__ X, const float* __restrict__ W,
    const float* __restrict__ bias, float* __restrict__ C,
    const float* __restrict__ maskScale)
{
    extern __shared__ float gsm[];   // 2 stages
    const uint32_t gsb = smem_u32(gsm);

    const int tid  = threadIdx.x;
    const int lane = tid & 31;
    const int warp = tid >> 5;
    const int g    = lane >> 2;
    const int tg   = lane & 3;
    const int wm   = warp >> 1;   // 0..3
    const int wn   = warp & 1;    // 0..1
    const int m0   = blockIdx.y * 128;
    const int n0   = blockIdx.x * 128;

    // LDSM per-thread address components (bytes)
    // A (Xs): matrices 0/1 = rows rb..rb+15 col 0; matrices 2/3 = same rows col+4.
    const uint32_t a_thr = (uint32_t)(((wm * 32 + (lane & 15)) * 36 + (lane >> 4) * 4) * 4);
    // B (Ws): matrices 0/1 = n-rows 0..7 of block, cols 0/+4; matrices 2/3 = n-rows 8..15.
    const uint32_t b_thr = (uint32_t)(((wn * 64 + ((lane >> 4) * 8) + (lane & 7)) * 36
                                      + (((lane >> 3) & 1) * 4)) * 4);

    float4 px[4], pw[4];   // prefetch regs

    auto ldg_tile = [&](int kt) {
#pragma unroll
        for (int i = 0; i < 4; i++) {
            int idx = i * 256 + tid;
            int xr = idx >> 3, xc = (idx & 7) * 4;     // X: 128 rows x 8 quads
            px[i] = *(const float4*)&X[(size_t)(m0 + xr) * 1024 + kt + xc];
        }
        const int bn = tid & 127;                      // W: column n handled
        const int bh = tid >> 7;                       // k-quad group
#pragma unroll
        for (int j = 0; j < 4; j++) {
            int kq = bh * 4 + j;
            pw[j] = make_float4(
                W[(size_t)(kt + kq * 4 + 0) * 1024 + n0 + bn],
                W[(size_t)(kt + kq * 4 + 1) * 1024 + n0 + bn],
                W[(size_t)(kt + kq * 4 + 2) * 1024 + n0 + bn],
                W[(size_t)(kt + kq * 4 + 3) * 1024 + n0 + bn]);
        }
    };
    auto sts_tile = [&](int st) {
        float* Xs = gsm + st * GSTG;
        float* Ws = Xs + GXF;
#pragma unroll
        for (int i = 0; i < 4; i++) {
            int idx = i * 256 + tid;
            int xr = idx >> 3, xc = (idx & 7) * 4;
            *(float4*)&Xs[xr * 36 + xc] = tf4(px[i]);
        }
        const int bn = tid & 127;
        const int bh = tid >> 7;
#pragma unroll
        for (int j = 0; j < 4; j++) {
            int kq = bh * 4 + j;
            *(float4*)&Ws[bn * 36 + kq * 4] = tf4(pw[j]);   // n-major rows
        }
    };

    float c[2][8][4];
#pragma unroll
    for (int mt = 0; mt < 2; mt++)
#pragma unroll
        for (int nt = 0; nt < 8; nt++)
#pragma unroll
            for (int e = 0; e < 4; e++) c[mt][nt][e] = 0.f;

    ldg_tile(0);
    sts_tile(0);
    __syncthreads();

    for (int kt = 0; kt < 32; kt++) {
        if (kt + 1 < 32) ldg_tile((kt + 1) * 32);

        const uint32_t xa = gsb + (kt & 1) * GSTGB + a_thr;
        const uint32_t wa = gsb + (kt & 1) * GSTGB + GXF * 4 + b_thr;

#pragma unroll
        for (int kk = 0; kk < 4; kk++) {               // k-steps of 8
            uint32_t af[2][4], bf[4][4];
            ldsm_x4(af[0], xa + kk * 32);              // mt 0 (+8 k-floats = 32B)
            ldsm_x4(af[1], xa + 16 * 36 * 4 + kk * 32);// mt 1
#pragma unroll
            for (int p = 0; p < 4; p++)
                ldsm_x4(bf[p], wa + p * (16 * 36 * 4) + kk * 32);
#pragma unroll
            for (int p = 0; p < 4; p++) {
                mma8(c[0][2 * p],     af[0], &bf[p][0]);
                mma8(c[0][2 * p + 1], af[0], &bf[p][2]);
                mma8(c[1][2 * p],     af[1], &bf[p][0]);
                mma8(c[1][2 * p + 1], af[1], &bf[p][2]);
            }
        }

        if (kt + 1 < 32) sts_tile((kt + 1) & 1);
        __syncthreads();
    }

    // Epilogue: bias, optional mask scale, store
#pragma unroll
    for (int mt = 0; mt < 2; mt++) {
        int r0 = m0 + wm * 32 + mt * 16 + g;
        int r1 = r0 + 8;
        float sc0 = 1.f, sc1 = 1.f;
        if (maskScale) {
            sc0 = maskScale[(size_t)r0 * TT];
            sc1 = maskScale[(size_t)r1 * TT];
        }
#pragma unroll
        for (int nt = 0; nt < 8; nt++) {
            int col = n0 + wn * 64 + nt * 8 + 2 * tg;
            float b0 = bias[col], b1 = bias[col + 1];
            float2 v0 = make_float2((c[mt][nt][0] + b0) * sc0, (c[mt][nt][1] + b1) * sc0);
            float2 v1 = make_float2((c[mt][nt][2] + b0) * sc1, (c[mt][nt][3] + b1) * sc1);
            *(float2*)&C[(size_t)r0 * 1024 + col] = v0;
            *(float2*)&C[(size_t)r1 * 1024 + col] = v1;
        }
    }
}

// ---------------- Flash attention v4 (LDSM fragments) ----------------
// Grid: (S/128, H, B). 128 threads = 4 warps; warp w owns q-rows [32w,32w+32)
// as 2 m-tiles. Ks: [t][d] stride 68 (LDSM rows = d-contiguous, n=t).
// Vs: [d][t] stride 68 (transposed fill; LDSM rows = t-contiguous, n=d).
// P round-trips through Qs (own warp rows only).
#define LDS_  68
#define FCH   64
#define NCH   (TT / FCH)

__global__ void __launch_bounds__(128) flash_attn_kernel(
    const float* __restrict__ mask, const int* __restrict__ causal_p)
{
    extern __shared__ float sm[];
    float* Qs = sm;                     // 128 x 68
    float* Ks = sm + 128 * LDS_;        // 64 x 68  [t][d]
    float* Vs = sm + 192 * LDS_;        // 64 x 68  [d][t]

    const int tid  = threadIdx.x;
    const int lane = tid & 31;
    const int warp = tid >> 5;
    const int g    = lane >> 2;
    const int tg   = lane & 3;
    const int s0   = blockIdx.x * 128;
    const int h    = blockIdx.y;
    const int b    = blockIdx.z;
    const int causal = causal_p[0];

    const uint32_t Qs_u = smem_u32(Qs);
    const uint32_t Ks_u = smem_u32(Ks);
    const uint32_t Vs_u = smem_u32(Vs);

    // LDSM per-thread bases (bytes)
    // B-operand (K and V): matrices 0/1 = rows 0..7 of block cols 0/+4; 2/3 = rows 8..15.
    const uint32_t bK = Ks_u + (uint32_t)(((((lane >> 4) * 8) + (lane & 7)) * LDS_
                                           + (((lane >> 3) & 1) * 4)) * 4);
    const uint32_t bV = Vs_u + (uint32_t)(((((lane >> 4) * 8) + (lane & 7)) * LDS_
                                           + (((lane >> 3) & 1) * 4)) * 4);
    // A-operand (Q / P in Qs): rows rb + (lane&15), col-half by bit4
    const uint32_t aP0 = Qs_u + (uint32_t)(((warp * 32 + (lane & 15)) * LDS_
                                            + ((lane >> 4) * 4)) * 4);
    const uint32_t aP1 = aP0 + (uint32_t)(16 * LDS_ * 4);

    // Load Q tile [128 x 64] -> smem (tf32-rounded)
    const size_t qoff = ((size_t)b * SS + s0) * CHN + h * HD;
#pragma unroll
    for (int i = 0; i < 16; i++) {
        int idx = i * 128 + tid;
        int r = idx >> 4, cc = (idx & 15) * 4;
        float4 v = *(const float4*)&g_Q[qoff + (size_t)r * CHN + cc];
        *(float4*)&Qs[r * LDS_ + cc] = tf4(v);
    }
    __syncthreads();

    // Persistent Q fragments via LDSM (same values as before, fewer ops)
    uint32_t qa[2][8][4];
#pragma unroll
    for (int mt = 0; mt < 2; mt++) {
        uint32_t base = (mt == 0) ? aP0 : aP1;
#pragma unroll
        for (int j = 0; j < 8; j++) ldsm_x4(qa[mt][j], base + j * 32);
    }

    float o[2][8][4];
#pragma unroll
    for (int mt = 0; mt < 2; mt++)
#pragma unroll
        for (int nt = 0; nt < 8; nt++)
#pragma unroll
            for (int e = 0; e < 4; e++) o[mt][nt][e] = 0.f;
    float mr[2][2] = {{-1e30f, -1e30f}, {-1e30f, -1e30f}};
    float lr[2][2] = {{0.f, 0.f}, {0.f, 0.f}};

    const float* mb = mask + (size_t)b * SS * TT;
    const int vd  = tid & 63;     // V transpose: this thread's d row
    const int vth = tid >> 6;

    for (int ic = 0; ic < NCH; ic++) {
        const int t0 = ic * FCH;
        __syncthreads();

        const size_t kvoff = ((size_t)b * TT + t0) * CHN + h * HD;
        // K fill [t][d] (vectorized)
#pragma unroll
        for (int i = 0; i < 8; i++) {
            int idx = i * 128 + tid;
            int r = idx >> 4, cc = (idx & 15) * 4;
            float4 kv = *(const float4*)&g_K[kvoff + (size_t)r * CHN + cc];
            *(float4*)&Ks[r * LDS_ + cc] = tf4(kv);
        }
        // V fill transposed [d][t]: thread owns row d=vd, 8 t-quads
#pragma unroll
        for (int q8 = 0; q8 < 8; q8++) {
            int q = vth * 8 + q8;   // t-quad 0..15
            float4 vv = make_float4(
                g_V[kvoff + (size_t)(q * 4 + 0) * CHN + vd],
                g_V[kvoff + (size_t)(q * 4 + 1) * CHN + vd],
                g_V[kvoff + (size_t)(q * 4 + 2) * CHN + vd],
                g_V[kvoff + (size_t)(q * 4 + 3) * CHN + vd]);
            *(float4*)&Vs[vd * LDS_ + q * 4] = tf4(vv);
        }
        __syncthreads();

        // S = Q K^T (LDSM B-frags; each feeds both m-tiles)
        float s[2][8][4];
#pragma unroll
        for (int mt = 0; mt < 2; mt++)
#pragma unroll
            for (int nt = 0; nt < 8; nt++)
#pragma unroll
                for (int e = 0; e < 4; e++) s[mt][nt][e] = 0.f;
#pragma unroll
        for (int ks = 0; ks < 8; ks++) {
            uint32_t kf[4][4];
#pragma unroll
            for (int p = 0; p < 4; p++)
                ldsm_x4(kf[p], bK + p * (16 * LDS_ * 4) + ks * 32);
#pragma unroll
            for (int p = 0; p < 4; p++) {
                mma8(s[0][2 * p],     qa[0][ks], &kf[p][0]);
                mma8(s[0][2 * p + 1], qa[0][ks], &kf[p][2]);
                mma8(s[1][2 * p],     qa[1][ks], &kf[p][0]);
                mma8(s[1][2 * p + 1], qa[1][ks], &kf[p][2]);
            }
        }

        // Scale + mask (reference semantics)
        if (!causal) {
            bool mz[8][2];
#pragma unroll
            for (int nt = 0; nt < 8; nt++)
#pragma unroll
                for (int e = 0; e < 2; e++)
                    mz[nt][e] = (mb[t0 + nt * 8 + 2 * tg + e] == 0.f);
#pragma unroll
            for (int mt = 0; mt < 2; mt++)
#pragma unroll
                for (int nt = 0; nt < 8; nt++)
#pragma unroll
                    for (int e = 0; e < 2; e++) {
                        s[mt][nt][e]     = mz[nt][e] ? -1e30f : s[mt][nt][e] * 0.125f;
                        s[mt][nt][2 + e] = mz[nt][e] ? -1e30f : s[mt][nt][2 + e] * 0.125f;
                    }
        } else {
#pragma unroll
            for (int mt = 0; mt < 2; mt++) {
                int rg0 = s0 + warp * 32 + mt * 16 + g;
                int rg1 = rg0 + 8;
#pragma unroll
                for (int nt = 0; nt < 8; nt++) {
#pragma unroll
                    for (int e = 0; e < 2; e++) {
                        int t = t0 + nt * 8 + 2 * tg + e;
                        float v0 = s[mt][nt][e] * 0.125f;
                        float v1 = s[mt][nt][2 + e] * 0.125f;
                        if (mb[(size_t)rg0 * TT + t] == 0.f && t <= rg0) v0 = -1e30f;
                        if (mb[(size_t)rg1 * TT + t] == 0.f && t <= rg1) v1 = -1e30f;
                        s[mt][nt][e] = v0;
                        s[mt][nt][2 + e] = v1;
                    }
                }
            }
        }

        // Online softmax; write P into Qs region (own rows only)
#pragma unroll
        for (int mt = 0; mt < 2; mt++) {
            float rm0 = -1e30f, rm1 = -1e30f;
#pragma unroll
            for (int nt = 0; nt < 8; nt++) {
                rm0 = fmaxf(rm0, fmaxf(s[mt][nt][0], s[mt][nt][1]));
                rm1 = fmaxf(rm1, fmaxf(s[mt][nt][2], s[mt][nt][3]));
            }
            rm0 = fmaxf(rm0, __shfl_xor_sync(0xffffffffu, rm0, 1));
            rm0 = fmaxf(rm0, __shfl_xor_sync(0xffffffffu, rm0, 2));
            rm1 = fmaxf(rm1, __shfl_xor_sync(0xffffffffu, rm1, 1));
            rm1 = fmaxf(rm1, __shfl_xor_sync(0xffffffffu, rm1, 2));

            float mn0 = fmaxf(mr[mt][0], rm0);
            float mn1 = fmaxf(mr[mt][1], rm1);
            float a0 = __expf(mr[mt][0] - mn0);
            float a1 = __expf(mr[mt][1] - mn1);
            mr[mt][0] = mn0; mr[mt][1] = mn1;

            int rb = warp * 32 + mt * 16;
            float ls0 = 0.f, ls1 = 0.f;
#pragma unroll
            for (int nt = 0; nt < 8; nt++) {
                float p00 = __expf(s[mt][nt][0] - mn0);
                float p01 = __expf(s[mt][nt][1] - mn0);
                float p10 = __expf(s[mt][nt][2] - mn1);
                float p11 = __expf(s[mt][nt][3] - mn1);
                ls0 += p00 + p01;
                ls1 += p10 + p11;
                int cb = nt * 8 + 2 * tg;
                *(float2*)&Qs[(rb + g) * LDS_ + cb] =
                    make_float2(f2tf_f(p00), f2tf_f(p01));
                *(float2*)&Qs[(rb + g + 8) * LDS_ + cb] =
                    make_float2(f2tf_f(p10), f2tf_f(p11));
                o[mt][nt][0] *= a0; o[mt][nt][1] *= a0;
                o[mt][nt][2] *= a1; o[mt][nt][3] *= a1;
            }
            ls0 += __shfl_xor_sync(0xffffffffu, ls0, 1);
            ls0 += __shfl_xor_sync(0xffffffffu, ls0, 2);
            ls1 += __shfl_xor_sync(0xffffffffu, ls1, 1);
            ls1 += __shfl_xor_sync(0xffffffffu, ls1, 2);
            lr[mt][0] = lr[mt][0] * a0 + ls0;
            lr[mt][1] = lr[mt][1] * a1 + ls1;
        }
        __syncwarp();   // P visible within warp before LDSM of own rows

        // O += P V (LDSM A from Qs/P, LDSM B from Vs[d][t])
#pragma unroll
        for (int ks = 0; ks < 8; ks++) {
            uint32_t pf[2][4], vf[4][4];
            ldsm_x4(pf[0], aP0 + ks * 32);
            ldsm_x4(pf[1], aP1 + ks * 32);
#pragma unroll
            for (int p = 0; p < 4; p++)
                ldsm_x4(vf[p], bV + p * (16 * LDS_ * 4) + ks * 32);
#pragma unroll
            for (int p = 0; p < 4; p++) {
                mma8(o[0][2 * p],     pf[0], &vf[p][0]);
                mma8(o[0][2 * p + 1], pf[0], &vf[p][2]);
                mma8(o[1][2 * p],     pf[1], &vf[p][0]);
                mma8(o[1][2 * p + 1], pf[1], &vf[p][2]);
            }
        }
    }

    // Normalize and write out
#pragma unroll
    for (int mt = 0; mt < 2; mt++) {
        float i0 = 1.f / lr[mt][0];
        float i1 = 1.f / lr[mt][1];
        const size_t ob = ((size_t)b * SS + s0 + warp * 32 + mt * 16) * CHN + h * HD;
#pragma unroll
        for (int nt = 0; nt < 8; nt++) {
            int col = nt * 8 + 2 * tg;
            float2 v0 = make_float2(o[mt][nt][0] * i0, o[mt][nt][1] * i0);
            float2 v1 = make_float2(o[mt][nt][2] * i1, o[mt][nt][3] * i1);
            *(float2*)&g_A[ob + (size_t)g * CHN + col] = v0;
            *(float2*)&g_A[ob + (size_t)(g + 8) * CHN + col] = v1;
        }
    }
}

// ---------------- launch ----------------
extern "C" void kernel_launch(void* const* d_in, const int* in_sizes, int n_in,
                              void* d_out, int out_size)
{
    const float* query = (const float*)d_in[0];
    const float* key   = (const float*)d_in[1];
    const float* value = (const float*)d_in[2];
    const float* mask  = (const float*)d_in[3];
    const float* Wq    = (const float*)d_in[4];
    const float* bq    = (const float*)d_in[5];
    const float* Wk    = (const float*)d_in[6];
    const float* bk    = (const float*)d_in[7];
    const float* Wv    = (const float*)d_in[8];
    const float* bv    = (const float*)d_in[9];
    const float* Wo    = (const float*)d_in[10];
    const float* bo    = (const float*)d_in[11];
    const int*   causal = (const int*)d_in[12];
    float* out = (float*)d_out;

    float *Qp, *Kp, *Vp, *Ap;
    cudaGetSymbolAddress((void**)&Qp, g_Q);
    cudaGetSymbolAddress((void**)&Kp, g_K);
    cudaGetSymbolAddress((void**)&Vp, g_V);
    cudaGetSymbolAddress((void**)&Ap, g_A);

    const int gsmem = 2 * GSTGB;   // 73,728 B
    cudaFuncSetAttribute(gemm_bias_kernel,
                         cudaFuncAttributeMaxDynamicSharedMemorySize, gsmem);

    dim3 ggrid(8, 32);   // N/128, M/128
    gemm_bias_kernel<<<ggrid, 256, gsmem>>>(query, Wq, bq, Qp, nullptr);
    gemm_bias_kernel<<<ggrid, 256, gsmem>>>(key,   Wk, bk, Kp, nullptr);
    gemm_bias_kernel<<<ggrid, 256, gsmem>>>(value, Wv, bv, Vp, nullptr);

    const int fsmem = 256 * LDS_ * (int)sizeof(float);   // 69,632 B
    cudaFuncSetAttribute(flash_attn_kernel,
                         cudaFuncAttributeMaxDynamicSharedMemorySize, fsmem);
    flash_attn_kernel<<<dim3(SS / 128, NH, BB), 128, fsmem>>>(mask, causal);

    gemm_bias_kernel<<<ggrid, 256, gsmem>>>(Ap, Wo, bo, out, mask);
}